// round 10
// baseline (speedup 1.0000x reference)
#include <cuda_runtime.h>
#include <cuda_fp16.h>
#include <cstdint>

#define M_DIM 8192
#define N_DIM 4096
#define K_DIM 4096

#define BM 256                  // x rows per CTA
#define BN 128                  // w rows per CTA
#define BK 64                   // K elements per stage (128 bytes/row)
#define STAGES 3
#define NTHREADS 512
#define NITER (K_DIM / BK)      // 64
#define A_HALVES (BM * BK)      // 16384
#define B_HALVES (BN * BK)      // 8192
#define STAGE_HALVES (A_HALVES + B_HALVES)       // 24576 (48KB)
#define SMEM_BYTES (STAGES * STAGE_HALVES * 2)   // 144KB

// Scratch: fp16 quant-dequantized x and w.
__device__ __half g_xh[(size_t)M_DIM * K_DIM];
__device__ __half g_wh[(size_t)N_DIM * K_DIM];

// ---------------------------------------------------------------------------
// Quant kernel (proven fast variant): quad per 16-elem NVFP4 block, one
// divide per thread.
// ---------------------------------------------------------------------------
__global__ void quant_kernel(const float* __restrict__ src, int is_w, int nquads)
{
    int t = blockIdx.x * blockDim.x + threadIdx.x;
    int quad = t >> 2;
    int lq = t & 3;
    if (quad >= nquads) return;

    __half* __restrict__ H = is_w ? g_wh : g_xh;

    size_t base = (size_t)quad * 16 + (size_t)lq * 4;
    float4 v = *reinterpret_cast<const float4*>(src + base);

    float amax = fmaxf(fmaxf(fabsf(v.x), fabsf(v.y)), fmaxf(fabsf(v.z), fabsf(v.w)));
    amax = fmaxf(amax, __shfl_xor_sync(0xffffffffu, amax, 1));
    amax = fmaxf(amax, __shfl_xor_sync(0xffffffffu, amax, 2));

    float scale = (amax > 0.0f) ? (amax / 6.0f) : 1.0f;
    float rinv  = 1.0f / scale;

    float vals[4] = {v.x, v.y, v.z, v.w};
    unsigned short hs[4];
#pragma unroll
    for (int i = 0; i < 4; i++) {
        float y = vals[i] * rinv;
        float a = fabsf(y);
        a = fminf(a, 6.0f);
        if (a <= 2.0f)       a = rintf(a * 2.0f) * 0.5f;
        else if (a <= 4.0f)  a = rintf(a);
        else                 a = rintf(a * 0.5f) * 2.0f;
        float q  = copysignf(a, y);
        float xq = q * scale;
        hs[i] = __half_as_ushort(__float2half_rn(xq));
    }
    uint2 hp;
    hp.x = (unsigned)hs[0] | ((unsigned)hs[1] << 16);
    hp.y = (unsigned)hs[2] | ((unsigned)hs[3] << 16);
    *reinterpret_cast<uint2*>(H + base) = hp;
}

// ---------------------------------------------------------------------------
// GEMM: C = Xq * Wq^T (+ bias). 256x128 CTA, 512 threads (16 warps, 4m x 4n),
// warp tile 64x32 (same per-warp structure as the proven R5 config).
// BK=64, 3-stage cp.async pipe, one __syncthreads per iteration.
// ---------------------------------------------------------------------------
__device__ __forceinline__ unsigned sptr(const void* p)
{
    return (unsigned)__cvta_generic_to_shared(p);
}

__global__ __launch_bounds__(NTHREADS, 1)
void gemm_kernel(const float* __restrict__ bias, float* __restrict__ out)
{
    extern __shared__ __half smem[];

    const int tid  = threadIdx.x;
    const int warp = tid >> 5;
    const int lane = tid & 31;
    const int wm = warp >> 2;   // 0..3  (M: 4 x 64)
    const int wn = warp & 3;    // 0..3  (N: 4 x 32)
    const int mBase = blockIdx.y * BM;
    const int nBase = blockIdx.x * BN;

    float c[4][4][4];
#pragma unroll
    for (int i = 0; i < 4; i++)
#pragma unroll
        for (int j = 0; j < 4; j++)
#pragma unroll
            for (int r = 0; r < 4; r++) c[i][j][r] = 0.0f;

    // 16B-chunk swizzle within a 128B row: chunk' = cc ^ (r & 7)
    auto load_tile = [&](int it, int buf) {
        int kk = it * BK;
        __half* sA = smem + buf * STAGE_HALVES;
        __half* sB = sA + A_HALVES;
        const __half* Ab = g_xh + (size_t)mBase * K_DIM + kk;
        const __half* Bb = g_wh + (size_t)nBase * K_DIM + kk;
#pragma unroll
        for (int h = 0; h < 4; h++) {        // A: 256 rows x 8 chunks = 2048
            int q  = tid + h * NTHREADS;     // 0..2047
            int r  = q >> 3;                 // row 0..255
            int cc = q & 7;
            int sw = r * BK + ((cc ^ (r & 7)) << 3);
            asm volatile("cp.async.cg.shared.global [%0], [%1], 16;\n"
                         :: "r"(sptr(sA + sw)), "l"(Ab + (size_t)r * K_DIM + (cc << 3)));
        }
#pragma unroll
        for (int h = 0; h < 2; h++) {        // B: 128 rows x 8 chunks = 1024
            int q  = tid + h * NTHREADS;     // 0..1023
            int r  = q >> 3;                 // row 0..127
            int cc = q & 7;
            int sw = r * BK + ((cc ^ (r & 7)) << 3);
            asm volatile("cp.async.cg.shared.global [%0], [%1], 16;\n"
                         :: "r"(sptr(sB + sw)), "l"(Bb + (size_t)r * K_DIM + (cc << 3)));
        }
        asm volatile("cp.async.commit_group;\n");
    };

    load_tile(0, 0);
    load_tile(1, 1);

    int buf = 0;
    for (int it = 0; it < NITER; it++) {
        asm volatile("cp.async.wait_group 1;\n");   // stage `it` resident
        __syncthreads();                            // all done with stage it-1

        if (it + 2 < NITER) {
            int nb = buf + 2; if (nb >= STAGES) nb -= STAGES;  // slot of it-1
            load_tile(it + 2, nb);
        }

        const __half* sA = smem + buf * STAGE_HALVES;
        const __half* sB = sA + A_HALVES;

#pragma unroll
        for (int ks = 0; ks < 4; ks++) {    // four k16 steps per BK=64
            unsigned af[4][4];
#pragma unroll
            for (int mi = 0; mi < 4; mi++) {
                int mat = lane >> 3;
                int r   = wm * 64 + mi * 16 + ((mat & 1) << 3) + (lane & 7);
                int cc  = ks * 2 + (mat >> 1);
                int sw  = r * BK + ((cc ^ (r & 7)) << 3);
                asm volatile(
                    "ldmatrix.sync.aligned.m8n8.x4.shared.b16 {%0,%1,%2,%3}, [%4];\n"
                    : "=r"(af[mi][0]), "=r"(af[mi][1]), "=r"(af[mi][2]), "=r"(af[mi][3])
                    : "r"(sptr(sA + sw)));
            }
            unsigned bf[4][2];
#pragma unroll
            for (int p = 0; p < 2; p++) {
                int mat = lane >> 3;
                int r   = wn * 32 + p * 16 + ((mat >> 1) << 3) + (lane & 7);
                int cc  = ks * 2 + (mat & 1);
                int sw  = r * BK + ((cc ^ (r & 7)) << 3);
                unsigned r0, r1, r2, r3;
                asm volatile(
                    "ldmatrix.sync.aligned.m8n8.x4.shared.b16 {%0,%1,%2,%3}, [%4];\n"
                    : "=r"(r0), "=r"(r1), "=r"(r2), "=r"(r3)
                    : "r"(sptr(sB + sw)));
                bf[p * 2][0]     = r0;
                bf[p * 2][1]     = r1;
                bf[p * 2 + 1][0] = r2;
                bf[p * 2 + 1][1] = r3;
            }
#pragma unroll
            for (int mi = 0; mi < 4; mi++)
#pragma unroll
                for (int ni = 0; ni < 4; ni++) {
                    asm volatile(
                        "mma.sync.aligned.m16n8k16.row.col.f32.f16.f16.f32 "
                        "{%0,%1,%2,%3}, {%4,%5,%6,%7}, {%8,%9}, {%0,%1,%2,%3};\n"
                        : "+f"(c[mi][ni][0]), "+f"(c[mi][ni][1]),
                          "+f"(c[mi][ni][2]), "+f"(c[mi][ni][3])
                        : "r"(af[mi][0]), "r"(af[mi][1]), "r"(af[mi][2]), "r"(af[mi][3]),
                          "r"(bf[ni][0]), "r"(bf[ni][1]));
                }
        }

        if (++buf == STAGES) buf = 0;
    }

    // Epilogue: bias add + fp32 store
#pragma unroll
    for (int mi = 0; mi < 4; mi++) {
        int row0 = mBase + wm * 64 + mi * 16 + (lane >> 2);
#pragma unroll
        for (int ni = 0; ni < 4; ni++) {
            int col = nBase + wn * 32 + ni * 8 + ((lane & 3) << 1);
            float b0 = __ldg(bias + col);
            float b1 = __ldg(bias + col + 1);
            out[(size_t)row0 * N_DIM + col]           = c[mi][ni][0] + b0;
            out[(size_t)row0 * N_DIM + col + 1]       = c[mi][ni][1] + b1;
            out[(size_t)(row0 + 8) * N_DIM + col]     = c[mi][ni][2] + b0;
            out[(size_t)(row0 + 8) * N_DIM + col + 1] = c[mi][ni][3] + b1;
        }
    }
}

// ---------------------------------------------------------------------------
extern "C" void kernel_launch(void* const* d_in, const int* in_sizes, int n_in,
                              void* d_out, int out_size)
{
    const float* x    = (const float*)d_in[0];
    const float* w    = (const float*)d_in[1];
    const float* bias = (const float*)d_in[2];
    float* out        = (float*)d_out;

    const int xquads = M_DIM * K_DIM / 16;
    const int wquads = N_DIM * K_DIM / 16;

    quant_kernel<<<(xquads * 4 + 255) / 256, 256>>>(x, 0, xquads);
    quant_kernel<<<(wquads * 4 + 255) / 256, 256>>>(w, 1, wquads);

    cudaFuncSetAttribute(gemm_kernel,
                         cudaFuncAttributeMaxDynamicSharedMemorySize, SMEM_BYTES);
    dim3 grid(N_DIM / BN, M_DIM / BM);
    gemm_kernel<<<grid, NTHREADS, SMEM_BYTES>>>(bias, out);
}

// round 12
// speedup vs baseline: 1.1089x; 1.1089x over previous
#include <cuda_runtime.h>
#include <cuda_fp16.h>
#include <cstdint>

#define M_DIM 8192
#define N_DIM 4096
#define K_DIM 4096

#define BM 128
#define BN 128
#define BK 64                   // K elements per stage (128 bytes/row)
#define STAGES 3
#define NITER (K_DIM / BK)      // 64
#define STAGE_HALVES (BM * BK + BN * BK)        // 16384 (32KB)
#define SMEM_BYTES (STAGES * STAGE_HALVES * 2)  // 96KB -> 2 CTAs/SM

// Scratch: fp16 quant-dequantized x and w.
__device__ __half g_xh[(size_t)M_DIM * K_DIM];
__device__ __half g_wh[(size_t)N_DIM * K_DIM];

// ---------------------------------------------------------------------------
// Quant kernel (proven fast variant): quad per 16-elem NVFP4 block, one
// divide per thread (1/scale), then multiplies.
// ---------------------------------------------------------------------------
__global__ void quant_kernel(const float* __restrict__ src, int is_w, int nquads)
{
    int t = blockIdx.x * blockDim.x + threadIdx.x;
    int quad = t >> 2;
    int lq = t & 3;
    if (quad >= nquads) return;

    __half* __restrict__ H = is_w ? g_wh : g_xh;

    size_t base = (size_t)quad * 16 + (size_t)lq * 4;
    float4 v = *reinterpret_cast<const float4*>(src + base);

    float amax = fmaxf(fmaxf(fabsf(v.x), fabsf(v.y)), fmaxf(fabsf(v.z), fabsf(v.w)));
    amax = fmaxf(amax, __shfl_xor_sync(0xffffffffu, amax, 1));
    amax = fmaxf(amax, __shfl_xor_sync(0xffffffffu, amax, 2));

    float scale = (amax > 0.0f) ? (amax / 6.0f) : 1.0f;
    float rinv  = 1.0f / scale;

    float vals[4] = {v.x, v.y, v.z, v.w};
    unsigned short hs[4];
#pragma unroll
    for (int i = 0; i < 4; i++) {
        float y = vals[i] * rinv;
        float a = fabsf(y);
        a = fminf(a, 6.0f);
        if (a <= 2.0f)       a = rintf(a * 2.0f) * 0.5f;
        else if (a <= 4.0f)  a = rintf(a);
        else                 a = rintf(a * 0.5f) * 2.0f;
        float q  = copysignf(a, y);
        float xq = q * scale;
        hs[i] = __half_as_ushort(__float2half_rn(xq));
    }
    uint2 hp;
    hp.x = (unsigned)hs[0] | ((unsigned)hs[1] << 16);
    hp.y = (unsigned)hs[2] | ((unsigned)hs[3] << 16);
    *reinterpret_cast<uint2*>(H + base) = hp;
}

// ---------------------------------------------------------------------------
// GEMM: C = Xq * Wq^T (+ bias). Proven R5 config: 128x128 CTA, BK=64,
// 3-stage cp.async pipe, 8 warps (2m x 4n), warp tile 64x32, 2 CTAs/SM.
// Tweak: cp.async issue for stage it+2 is deferred until after the first
// k16 compute block, smoothing the per-iteration issue burst.
// ---------------------------------------------------------------------------
__device__ __forceinline__ unsigned sptr(const void* p)
{
    return (unsigned)__cvta_generic_to_shared(p);
}

__global__ __launch_bounds__(256, 2)
void gemm_kernel(const float* __restrict__ bias, float* __restrict__ out)
{
    extern __shared__ __half smem[];

    const int tid  = threadIdx.x;
    const int warp = tid >> 5;
    const int lane = tid & 31;
    const int wm = warp >> 2;   // 0..1
    const int wn = warp & 3;    // 0..3
    const int mBase = blockIdx.y * BM;
    const int nBase = blockIdx.x * BN;

    float c[4][4][4];
#pragma unroll
    for (int i = 0; i < 4; i++)
#pragma unroll
        for (int j = 0; j < 4; j++)
#pragma unroll
            for (int r = 0; r < 4; r++) c[i][j][r] = 0.0f;

    // 16B-chunk swizzle within a 128B row: chunk' = cc ^ (r & 7)
    auto load_tile = [&](int it, int buf) {
        int kk = it * BK;
        __half* sA = smem + buf * STAGE_HALVES;
        __half* sB = sA + BM * BK;
        const __half* Ab = g_xh + (size_t)mBase * K_DIM + kk;
        const __half* Bb = g_wh + (size_t)nBase * K_DIM + kk;
#pragma unroll
        for (int h = 0; h < 4; h++) {
            int q  = tid + h * 256;          // 0..1023
            int r  = q >> 3;                 // row 0..127
            int cc = q & 7;                  // 16B chunk 0..7
            int sw = r * BK + ((cc ^ (r & 7)) << 3);
            asm volatile("cp.async.cg.shared.global [%0], [%1], 16;\n"
                         :: "r"(sptr(sA + sw)), "l"(Ab + (size_t)r * K_DIM + (cc << 3)));
            asm volatile("cp.async.cg.shared.global [%0], [%1], 16;\n"
                         :: "r"(sptr(sB + sw)), "l"(Bb + (size_t)r * K_DIM + (cc << 3)));
        }
        asm volatile("cp.async.commit_group;\n");
    };

    // Per-k16 compute block over the resident stage.
    auto compute_ks = [&](const __half* sA, const __half* sB, int ks) {
        unsigned af[4][4];
#pragma unroll
        for (int mi = 0; mi < 4; mi++) {
            int mat = lane >> 3;
            int r   = wm * 64 + mi * 16 + ((mat & 1) << 3) + (lane & 7);
            int cc  = ks * 2 + (mat >> 1);
            int sw  = r * BK + ((cc ^ (r & 7)) << 3);
            asm volatile(
                "ldmatrix.sync.aligned.m8n8.x4.shared.b16 {%0,%1,%2,%3}, [%4];\n"
                : "=r"(af[mi][0]), "=r"(af[mi][1]), "=r"(af[mi][2]), "=r"(af[mi][3])
                : "r"(sptr(sA + sw)));
        }
        unsigned bf[4][2];
#pragma unroll
        for (int p = 0; p < 2; p++) {
            int mat = lane >> 3;
            int r   = wn * 32 + p * 16 + ((mat >> 1) << 3) + (lane & 7);
            int cc  = ks * 2 + (mat & 1);
            int sw  = r * BK + ((cc ^ (r & 7)) << 3);
            unsigned r0, r1, r2, r3;
            asm volatile(
                "ldmatrix.sync.aligned.m8n8.x4.shared.b16 {%0,%1,%2,%3}, [%4];\n"
                : "=r"(r0), "=r"(r1), "=r"(r2), "=r"(r3)
                : "r"(sptr(sB + sw)));
            bf[p * 2][0]     = r0;
            bf[p * 2][1]     = r1;
            bf[p * 2 + 1][0] = r2;
            bf[p * 2 + 1][1] = r3;
        }
#pragma unroll
        for (int mi = 0; mi < 4; mi++)
#pragma unroll
            for (int ni = 0; ni < 4; ni++) {
                asm volatile(
                    "mma.sync.aligned.m16n8k16.row.col.f32.f16.f16.f32 "
                    "{%0,%1,%2,%3}, {%4,%5,%6,%7}, {%8,%9}, {%0,%1,%2,%3};\n"
                    : "+f"(c[mi][ni][0]), "+f"(c[mi][ni][1]),
                      "+f"(c[mi][ni][2]), "+f"(c[mi][ni][3])
                    : "r"(af[mi][0]), "r"(af[mi][1]), "r"(af[mi][2]), "r"(af[mi][3]),
                      "r"(bf[ni][0]), "r"(bf[ni][1]));
            }
    };

    // Prologue: stages 0 and 1
    load_tile(0, 0);
    load_tile(1, 1);

    int buf = 0;
    for (int it = 0; it < NITER; it++) {
        asm volatile("cp.async.wait_group 1;\n");   // stage `it` resident
        __syncthreads();                            // all done with stage it-1

        const __half* sA = smem + buf * STAGE_HALVES;
        const __half* sB = sA + BM * BK;

        // First k16 block before issuing next loads: HMMA pipe starts
        // immediately; LDGSTS issue burst is hidden behind it.
        compute_ks(sA, sB, 0);

        if (it + 2 < NITER) {
            int nb = buf + 2; if (nb >= STAGES) nb -= STAGES;  // slot of it-1
            load_tile(it + 2, nb);
        }

#pragma unroll
        for (int ks = 1; ks < 4; ks++)
            compute_ks(sA, sB, ks);

        if (++buf == STAGES) buf = 0;
    }

    // Epilogue: bias add + fp32 store
#pragma unroll
    for (int mi = 0; mi < 4; mi++) {
        int row0 = mBase + wm * 64 + mi * 16 + (lane >> 2);
#pragma unroll
        for (int ni = 0; ni < 4; ni++) {
            int col = nBase + wn * 32 + ni * 8 + ((lane & 3) << 1);
            float b0 = __ldg(bias + col);
            float b1 = __ldg(bias + col + 1);
            out[(size_t)row0 * N_DIM + col]           = c[mi][ni][0] + b0;
            out[(size_t)row0 * N_DIM + col + 1]       = c[mi][ni][1] + b1;
            out[(size_t)(row0 + 8) * N_DIM + col]     = c[mi][ni][2] + b0;
            out[(size_t)(row0 + 8) * N_DIM + col + 1] = c[mi][ni][3] + b1;
        }
    }
}

// ---------------------------------------------------------------------------
extern "C" void kernel_launch(void* const* d_in, const int* in_sizes, int n_in,
                              void* d_out, int out_size)
{
    const float* x    = (const float*)d_in[0];
    const float* w    = (const float*)d_in[1];
    const float* bias = (const float*)d_in[2];
    float* out        = (float*)d_out;

    const int xquads = M_DIM * K_DIM / 16;
    const int wquads = N_DIM * K_DIM / 16;

    quant_kernel<<<(xquads * 4 + 255) / 256, 256>>>(x, 0, xquads);
    quant_kernel<<<(wquads * 4 + 255) / 256, 256>>>(w, 1, wquads);

    cudaFuncSetAttribute(gemm_kernel,
                         cudaFuncAttributeMaxDynamicSharedMemorySize, SMEM_BYTES);
    dim3 grid(N_DIM / BN, M_DIM / BM);
    gemm_kernel<<<grid, 256, SMEM_BYTES>>>(bias, out);
}

// round 13
// speedup vs baseline: 1.1152x; 1.0057x over previous
#include <cuda_runtime.h>
#include <cuda_fp16.h>
#include <cstdint>

#define M_DIM 8192
#define N_DIM 4096
#define K_DIM 4096

#define BM 128
#define BN 128
#define BK 64                   // K elements per stage (128 bytes/row)
#define STAGES 3
#define NITER (K_DIM / BK)      // 64
#define STAGE_HALVES (BM * BK + BN * BK)        // 16384 (32KB)
#define SMEM_BYTES (STAGES * STAGE_HALVES * 2)  // 96KB -> 2 CTAs/SM

// Scratch: fp16 quant-dequantized x and w.
__device__ __half g_xh[(size_t)M_DIM * K_DIM];
__device__ __half g_wh[(size_t)N_DIM * K_DIM];

// ---------------------------------------------------------------------------
// Quant kernel (proven fast variant): quad per 16-elem NVFP4 block, one
// divide per thread (1/scale), then multiplies.
// ---------------------------------------------------------------------------
__global__ void quant_kernel(const float* __restrict__ src, int is_w, int nquads)
{
    int t = blockIdx.x * blockDim.x + threadIdx.x;
    int quad = t >> 2;
    int lq = t & 3;
    if (quad >= nquads) return;

    __half* __restrict__ H = is_w ? g_wh : g_xh;

    size_t base = (size_t)quad * 16 + (size_t)lq * 4;
    float4 v = *reinterpret_cast<const float4*>(src + base);

    float amax = fmaxf(fmaxf(fabsf(v.x), fabsf(v.y)), fmaxf(fabsf(v.z), fabsf(v.w)));
    amax = fmaxf(amax, __shfl_xor_sync(0xffffffffu, amax, 1));
    amax = fmaxf(amax, __shfl_xor_sync(0xffffffffu, amax, 2));

    float scale = (amax > 0.0f) ? (amax / 6.0f) : 1.0f;
    float rinv  = 1.0f / scale;

    float vals[4] = {v.x, v.y, v.z, v.w};
    unsigned short hs[4];
#pragma unroll
    for (int i = 0; i < 4; i++) {
        float y = vals[i] * rinv;
        float a = fabsf(y);
        a = fminf(a, 6.0f);
        if (a <= 2.0f)       a = rintf(a * 2.0f) * 0.5f;
        else if (a <= 4.0f)  a = rintf(a);
        else                 a = rintf(a * 0.5f) * 2.0f;
        float q  = copysignf(a, y);
        float xq = q * scale;
        hs[i] = __half_as_ushort(__float2half_rn(xq));
    }
    uint2 hp;
    hp.x = (unsigned)hs[0] | ((unsigned)hs[1] << 16);
    hp.y = (unsigned)hs[2] | ((unsigned)hs[3] << 16);
    *reinterpret_cast<uint2*>(H + base) = hp;
}

// ---------------------------------------------------------------------------
// GEMM: C = Xq * Wq^T (+ bias). Proven R5 config: 128x128 CTA, BK=64,
// 3-stage cp.async pipe, 8 warps (2m x 4n), warp tile 64x32, 2 CTAs/SM.
// Tweak: cp.async issue for stage it+2 is deferred until after the first
// k16 compute block, smoothing the per-iteration issue burst.
// ---------------------------------------------------------------------------
__device__ __forceinline__ unsigned sptr(const void* p)
{
    return (unsigned)__cvta_generic_to_shared(p);
}

__global__ __launch_bounds__(256, 2)
void gemm_kernel(const float* __restrict__ bias, float* __restrict__ out)
{
    extern __shared__ __half smem[];

    const int tid  = threadIdx.x;
    const int warp = tid >> 5;
    const int lane = tid & 31;
    const int wm = warp >> 2;   // 0..1
    const int wn = warp & 3;    // 0..3
    const int mBase = blockIdx.y * BM;
    const int nBase = blockIdx.x * BN;

    float c[4][4][4];
#pragma unroll
    for (int i = 0; i < 4; i++)
#pragma unroll
        for (int j = 0; j < 4; j++)
#pragma unroll
            for (int r = 0; r < 4; r++) c[i][j][r] = 0.0f;

    // 16B-chunk swizzle within a 128B row: chunk' = cc ^ (r & 7)
    auto load_tile = [&](int it, int buf) {
        int kk = it * BK;
        __half* sA = smem + buf * STAGE_HALVES;
        __half* sB = sA + BM * BK;
        const __half* Ab = g_xh + (size_t)mBase * K_DIM + kk;
        const __half* Bb = g_wh + (size_t)nBase * K_DIM + kk;
#pragma unroll
        for (int h = 0; h < 4; h++) {
            int q  = tid + h * 256;          // 0..1023
            int r  = q >> 3;                 // row 0..127
            int cc = q & 7;                  // 16B chunk 0..7
            int sw = r * BK + ((cc ^ (r & 7)) << 3);
            asm volatile("cp.async.cg.shared.global [%0], [%1], 16;\n"
                         :: "r"(sptr(sA + sw)), "l"(Ab + (size_t)r * K_DIM + (cc << 3)));
            asm volatile("cp.async.cg.shared.global [%0], [%1], 16;\n"
                         :: "r"(sptr(sB + sw)), "l"(Bb + (size_t)r * K_DIM + (cc << 3)));
        }
        asm volatile("cp.async.commit_group;\n");
    };

    // Per-k16 compute block over the resident stage.
    auto compute_ks = [&](const __half* sA, const __half* sB, int ks) {
        unsigned af[4][4];
#pragma unroll
        for (int mi = 0; mi < 4; mi++) {
            int mat = lane >> 3;
            int r   = wm * 64 + mi * 16 + ((mat & 1) << 3) + (lane & 7);
            int cc  = ks * 2 + (mat >> 1);
            int sw  = r * BK + ((cc ^ (r & 7)) << 3);
            asm volatile(
                "ldmatrix.sync.aligned.m8n8.x4.shared.b16 {%0,%1,%2,%3}, [%4];\n"
                : "=r"(af[mi][0]), "=r"(af[mi][1]), "=r"(af[mi][2]), "=r"(af[mi][3])
                : "r"(sptr(sA + sw)));
        }
        unsigned bf[4][2];
#pragma unroll
        for (int p = 0; p < 2; p++) {
            int mat = lane >> 3;
            int r   = wn * 32 + p * 16 + ((mat >> 1) << 3) + (lane & 7);
            int cc  = ks * 2 + (mat & 1);
            int sw  = r * BK + ((cc ^ (r & 7)) << 3);
            unsigned r0, r1, r2, r3;
            asm volatile(
                "ldmatrix.sync.aligned.m8n8.x4.shared.b16 {%0,%1,%2,%3}, [%4];\n"
                : "=r"(r0), "=r"(r1), "=r"(r2), "=r"(r3)
                : "r"(sptr(sB + sw)));
            bf[p * 2][0]     = r0;
            bf[p * 2][1]     = r1;
            bf[p * 2 + 1][0] = r2;
            bf[p * 2 + 1][1] = r3;
        }
#pragma unroll
        for (int mi = 0; mi < 4; mi++)
#pragma unroll
            for (int ni = 0; ni < 4; ni++) {
                asm volatile(
                    "mma.sync.aligned.m16n8k16.row.col.f32.f16.f16.f32 "
                    "{%0,%1,%2,%3}, {%4,%5,%6,%7}, {%8,%9}, {%0,%1,%2,%3};\n"
                    : "+f"(c[mi][ni][0]), "+f"(c[mi][ni][1]),
                      "+f"(c[mi][ni][2]), "+f"(c[mi][ni][3])
                    : "r"(af[mi][0]), "r"(af[mi][1]), "r"(af[mi][2]), "r"(af[mi][3]),
                      "r"(bf[ni][0]), "r"(bf[ni][1]));
            }
    };

    // Prologue: stages 0 and 1
    load_tile(0, 0);
    load_tile(1, 1);

    int buf = 0;
    for (int it = 0; it < NITER; it++) {
        asm volatile("cp.async.wait_group 1;\n");   // stage `it` resident
        __syncthreads();                            // all done with stage it-1

        const __half* sA = smem + buf * STAGE_HALVES;
        const __half* sB = sA + BM * BK;

        // First k16 block before issuing next loads: HMMA pipe starts
        // immediately; LDGSTS issue burst is hidden behind it.
        compute_ks(sA, sB, 0);

        if (it + 2 < NITER) {
            int nb = buf + 2; if (nb >= STAGES) nb -= STAGES;  // slot of it-1
            load_tile(it + 2, nb);
        }

#pragma unroll
        for (int ks = 1; ks < 4; ks++)
            compute_ks(sA, sB, ks);

        if (++buf == STAGES) buf = 0;
    }

    // Epilogue: bias add + fp32 store
#pragma unroll
    for (int mi = 0; mi < 4; mi++) {
        int row0 = mBase + wm * 64 + mi * 16 + (lane >> 2);
#pragma unroll
        for (int ni = 0; ni < 4; ni++) {
            int col = nBase + wn * 32 + ni * 8 + ((lane & 3) << 1);
            float b0 = __ldg(bias + col);
            float b1 = __ldg(bias + col + 1);
            out[(size_t)row0 * N_DIM + col]           = c[mi][ni][0] + b0;
            out[(size_t)row0 * N_DIM + col + 1]       = c[mi][ni][1] + b1;
            out[(size_t)(row0 + 8) * N_DIM + col]     = c[mi][ni][2] + b0;
            out[(size_t)(row0 + 8) * N_DIM + col + 1] = c[mi][ni][3] + b1;
        }
    }
}

// ---------------------------------------------------------------------------
extern "C" void kernel_launch(void* const* d_in, const int* in_sizes, int n_in,
                              void* d_out, int out_size)
{
    const float* x    = (const float*)d_in[0];
    const float* w    = (const float*)d_in[1];
    const float* bias = (const float*)d_in[2];
    float* out        = (float*)d_out;

    const int xquads = M_DIM * K_DIM / 16;
    const int wquads = N_DIM * K_DIM / 16;

    quant_kernel<<<(xquads * 4 + 255) / 256, 256>>>(x, 0, xquads);
    quant_kernel<<<(wquads * 4 + 255) / 256, 256>>>(w, 1, wquads);

    cudaFuncSetAttribute(gemm_kernel,
                         cudaFuncAttributeMaxDynamicSharedMemorySize, SMEM_BYTES);
    dim3 grid(N_DIM / BN, M_DIM / BM);
    gemm_kernel<<<grid, 256, SMEM_BYTES>>>(bias, out);
}

// round 14
// speedup vs baseline: 1.1179x; 1.0024x over previous
#include <cuda_runtime.h>
#include <cuda_fp16.h>
#include <cstdint>

#define M_DIM 8192
#define N_DIM 4096
#define K_DIM 4096

#define BM 128
#define BN 128
#define BK 64                   // K elements per stage (128 bytes/row)
#define STAGES 3
#define NITER (K_DIM / BK)      // 64
#define STAGE_HALVES (BM * BK + BN * BK)        // 16384 (32KB)
#define SMEM_BYTES (STAGES * STAGE_HALVES * 2)  // 96KB -> 2 CTAs/SM

// Scratch: fp16 quant-dequantized x and w.
__device__ __half g_xh[(size_t)M_DIM * K_DIM];
__device__ __half g_wh[(size_t)N_DIM * K_DIM];

// ---------------------------------------------------------------------------
// Quant kernel (proven fast variant): quad per 16-elem NVFP4 block, one
// divide per thread (1/scale), then multiplies.
// ---------------------------------------------------------------------------
__global__ void quant_kernel(const float* __restrict__ src, int is_w, int nquads)
{
    int t = blockIdx.x * blockDim.x + threadIdx.x;
    int quad = t >> 2;
    int lq = t & 3;
    if (quad >= nquads) return;

    __half* __restrict__ H = is_w ? g_wh : g_xh;

    size_t base = (size_t)quad * 16 + (size_t)lq * 4;
    float4 v = *reinterpret_cast<const float4*>(src + base);

    float amax = fmaxf(fmaxf(fabsf(v.x), fabsf(v.y)), fmaxf(fabsf(v.z), fabsf(v.w)));
    amax = fmaxf(amax, __shfl_xor_sync(0xffffffffu, amax, 1));
    amax = fmaxf(amax, __shfl_xor_sync(0xffffffffu, amax, 2));

    float scale = (amax > 0.0f) ? (amax / 6.0f) : 1.0f;
    float rinv  = 1.0f / scale;

    float vals[4] = {v.x, v.y, v.z, v.w};
    unsigned short hs[4];
#pragma unroll
    for (int i = 0; i < 4; i++) {
        float y = vals[i] * rinv;
        float a = fabsf(y);
        a = fminf(a, 6.0f);
        if (a <= 2.0f)       a = rintf(a * 2.0f) * 0.5f;
        else if (a <= 4.0f)  a = rintf(a);
        else                 a = rintf(a * 0.5f) * 2.0f;
        float q  = copysignf(a, y);
        float xq = q * scale;
        hs[i] = __half_as_ushort(__float2half_rn(xq));
    }
    uint2 hp;
    hp.x = (unsigned)hs[0] | ((unsigned)hs[1] << 16);
    hp.y = (unsigned)hs[2] | ((unsigned)hs[3] << 16);
    *reinterpret_cast<uint2*>(H + base) = hp;
}

// ---------------------------------------------------------------------------
// GEMM: C = Xq * Wq^T (+ bias). Proven R5 config: 128x128 CTA, BK=64,
// 3-stage cp.async pipe, 8 warps (2m x 4n), warp tile 64x32, 2 CTAs/SM.
// Tweak: cp.async issue for stage it+2 is deferred until after the first
// k16 compute block, smoothing the per-iteration issue burst.
// ---------------------------------------------------------------------------
__device__ __forceinline__ unsigned sptr(const void* p)
{
    return (unsigned)__cvta_generic_to_shared(p);
}

__global__ __launch_bounds__(256, 2)
void gemm_kernel(const float* __restrict__ bias, float* __restrict__ out)
{
    extern __shared__ __half smem[];

    const int tid  = threadIdx.x;
    const int warp = tid >> 5;
    const int lane = tid & 31;
    const int wm = warp >> 2;   // 0..1
    const int wn = warp & 3;    // 0..3
    const int mBase = blockIdx.y * BM;
    const int nBase = blockIdx.x * BN;

    float c[4][4][4];
#pragma unroll
    for (int i = 0; i < 4; i++)
#pragma unroll
        for (int j = 0; j < 4; j++)
#pragma unroll
            for (int r = 0; r < 4; r++) c[i][j][r] = 0.0f;

    // 16B-chunk swizzle within a 128B row: chunk' = cc ^ (r & 7)
    auto load_tile = [&](int it, int buf) {
        int kk = it * BK;
        __half* sA = smem + buf * STAGE_HALVES;
        __half* sB = sA + BM * BK;
        const __half* Ab = g_xh + (size_t)mBase * K_DIM + kk;
        const __half* Bb = g_wh + (size_t)nBase * K_DIM + kk;
#pragma unroll
        for (int h = 0; h < 4; h++) {
            int q  = tid + h * 256;          // 0..1023
            int r  = q >> 3;                 // row 0..127
            int cc = q & 7;                  // 16B chunk 0..7
            int sw = r * BK + ((cc ^ (r & 7)) << 3);
            asm volatile("cp.async.cg.shared.global [%0], [%1], 16;\n"
                         :: "r"(sptr(sA + sw)), "l"(Ab + (size_t)r * K_DIM + (cc << 3)));
            asm volatile("cp.async.cg.shared.global [%0], [%1], 16;\n"
                         :: "r"(sptr(sB + sw)), "l"(Bb + (size_t)r * K_DIM + (cc << 3)));
        }
        asm volatile("cp.async.commit_group;\n");
    };

    // Per-k16 compute block over the resident stage.
    auto compute_ks = [&](const __half* sA, const __half* sB, int ks) {
        unsigned af[4][4];
#pragma unroll
        for (int mi = 0; mi < 4; mi++) {
            int mat = lane >> 3;
            int r   = wm * 64 + mi * 16 + ((mat & 1) << 3) + (lane & 7);
            int cc  = ks * 2 + (mat >> 1);
            int sw  = r * BK + ((cc ^ (r & 7)) << 3);
            asm volatile(
                "ldmatrix.sync.aligned.m8n8.x4.shared.b16 {%0,%1,%2,%3}, [%4];\n"
                : "=r"(af[mi][0]), "=r"(af[mi][1]), "=r"(af[mi][2]), "=r"(af[mi][3])
                : "r"(sptr(sA + sw)));
        }
        unsigned bf[4][2];
#pragma unroll
        for (int p = 0; p < 2; p++) {
            int mat = lane >> 3;
            int r   = wn * 32 + p * 16 + ((mat >> 1) << 3) + (lane & 7);
            int cc  = ks * 2 + (mat & 1);
            int sw  = r * BK + ((cc ^ (r & 7)) << 3);
            unsigned r0, r1, r2, r3;
            asm volatile(
                "ldmatrix.sync.aligned.m8n8.x4.shared.b16 {%0,%1,%2,%3}, [%4];\n"
                : "=r"(r0), "=r"(r1), "=r"(r2), "=r"(r3)
                : "r"(sptr(sB + sw)));
            bf[p * 2][0]     = r0;
            bf[p * 2][1]     = r1;
            bf[p * 2 + 1][0] = r2;
            bf[p * 2 + 1][1] = r3;
        }
#pragma unroll
        for (int mi = 0; mi < 4; mi++)
#pragma unroll
            for (int ni = 0; ni < 4; ni++) {
                asm volatile(
                    "mma.sync.aligned.m16n8k16.row.col.f32.f16.f16.f32 "
                    "{%0,%1,%2,%3}, {%4,%5,%6,%7}, {%8,%9}, {%0,%1,%2,%3};\n"
                    : "+f"(c[mi][ni][0]), "+f"(c[mi][ni][1]),
                      "+f"(c[mi][ni][2]), "+f"(c[mi][ni][3])
                    : "r"(af[mi][0]), "r"(af[mi][1]), "r"(af[mi][2]), "r"(af[mi][3]),
                      "r"(bf[ni][0]), "r"(bf[ni][1]));
            }
    };

    // Prologue: stages 0 and 1
    load_tile(0, 0);
    load_tile(1, 1);

    int buf = 0;
    for (int it = 0; it < NITER; it++) {
        asm volatile("cp.async.wait_group 1;\n");   // stage `it` resident
        __syncthreads();                            // all done with stage it-1

        const __half* sA = smem + buf * STAGE_HALVES;
        const __half* sB = sA + BM * BK;

        // First k16 block before issuing next loads: HMMA pipe starts
        // immediately; LDGSTS issue burst is hidden behind it.
        compute_ks(sA, sB, 0);

        if (it + 2 < NITER) {
            int nb = buf + 2; if (nb >= STAGES) nb -= STAGES;  // slot of it-1
            load_tile(it + 2, nb);
        }

#pragma unroll
        for (int ks = 1; ks < 4; ks++)
            compute_ks(sA, sB, ks);

        if (++buf == STAGES) buf = 0;
    }

    // Epilogue: bias add + fp32 store
#pragma unroll
    for (int mi = 0; mi < 4; mi++) {
        int row0 = mBase + wm * 64 + mi * 16 + (lane >> 2);
#pragma unroll
        for (int ni = 0; ni < 4; ni++) {
            int col = nBase + wn * 32 + ni * 8 + ((lane & 3) << 1);
            float b0 = __ldg(bias + col);
            float b1 = __ldg(bias + col + 1);
            out[(size_t)row0 * N_DIM + col]           = c[mi][ni][0] + b0;
            out[(size_t)row0 * N_DIM + col + 1]       = c[mi][ni][1] + b1;
            out[(size_t)(row0 + 8) * N_DIM + col]     = c[mi][ni][2] + b0;
            out[(size_t)(row0 + 8) * N_DIM + col + 1] = c[mi][ni][3] + b1;
        }
    }
}

// ---------------------------------------------------------------------------
extern "C" void kernel_launch(void* const* d_in, const int* in_sizes, int n_in,
                              void* d_out, int out_size)
{
    const float* x    = (const float*)d_in[0];
    const float* w    = (const float*)d_in[1];
    const float* bias = (const float*)d_in[2];
    float* out        = (float*)d_out;

    const int xquads = M_DIM * K_DIM / 16;
    const int wquads = N_DIM * K_DIM / 16;

    quant_kernel<<<(xquads * 4 + 255) / 256, 256>>>(x, 0, xquads);
    quant_kernel<<<(wquads * 4 + 255) / 256, 256>>>(w, 1, wquads);

    cudaFuncSetAttribute(gemm_kernel,
                         cudaFuncAttributeMaxDynamicSharedMemorySize, SMEM_BYTES);
    dim3 grid(N_DIM / BN, M_DIM / BM);
    gemm_kernel<<<grid, 256, SMEM_BYTES>>>(bias, out);
}